// round 5
// baseline (speedup 1.0000x reference)
#include <cuda_runtime.h>
#include <cuda_bf16.h>
#include <cstdint>

#define N_NODES 50000
#define N_EDGES 600000
#define D 128
#define SCAN_BLK 1024
#define NB ((N_NODES + SCAN_BLK - 1) / SCAN_BLK)   // 49

// ---------------------------------------------------------------------------
// Scratch (device globals: allocation-free, graph-capturable)
// ---------------------------------------------------------------------------
__device__ int                g_deg_i[N_NODES];
__device__ int                g_cursor[N_NODES];
__device__ int                g_off[N_NODES + 1];
__device__ int                g_bsum[NB];
__device__ unsigned long long g_epack[N_EDGES];  // (norm_bits<<32)|src, CSR order
__device__ float              g_norm[N_NODES];
__device__ float              g_h1[N_NODES * D]; // layer-1 output (after relu)

// ---------------------------------------------------------------------------
// CSR build
// ---------------------------------------------------------------------------
__global__ void zero_kernel() {
    int i = blockIdx.x * blockDim.x + threadIdx.x;
    if (i < N_NODES) g_deg_i[i] = 0;
}

__global__ void hist_kernel(const int* __restrict__ dst) {
    int i = blockIdx.x * blockDim.x + threadIdx.x;
    if (i < N_EDGES) atomicAdd(&g_deg_i[dst[i]], 1);
}

__device__ __forceinline__ int warp_incl_scan(int x, int lane) {
    #pragma unroll
    for (int ofs = 1; ofs < 32; ofs <<= 1) {
        int t = __shfl_up_sync(0xFFFFFFFFu, x, ofs);
        if (lane >= ofs) x += t;
    }
    return x;
}

// Phase A: per-block inclusive scan of deg -> g_off (block-local), block sums.
__global__ __launch_bounds__(SCAN_BLK) void scanA_kernel() {
    __shared__ int wsum[32];
    int tid = threadIdx.x, lane = tid & 31, wid = tid >> 5;
    int idx = blockIdx.x * SCAN_BLK + tid;
    int v = (idx < N_NODES) ? g_deg_i[idx] : 0;
    int incl = warp_incl_scan(v, lane);
    if (lane == 31) wsum[wid] = incl;
    __syncthreads();
    if (wid == 0) {
        int s = wsum[lane];
        int si = warp_incl_scan(s, lane);
        wsum[lane] = si - s;
    }
    __syncthreads();
    int bincl = incl + wsum[wid];
    if (idx < N_NODES) g_off[idx] = bincl;       // block-local inclusive
    if (tid == SCAN_BLK - 1) g_bsum[blockIdx.x] = bincl;
}

// Phase C (scanB folded in): each block redundantly scans the 49 block sums,
// finalizes exclusive offsets, inits cursor (absolute) + norm.
__global__ __launch_bounds__(SCAN_BLK) void scanC_kernel() {
    __shared__ int s[NB];
    __shared__ int base_s;
    int tid = threadIdx.x;
    if (tid < NB) s[tid] = g_bsum[tid];
    __syncthreads();
    if (tid == 0) {
        int run = 0;
        int bid = blockIdx.x;
        #pragma unroll 1
        for (int i = 0; i < NB; i++) {
            if (i == bid) base_s = run;
            run += s[i];
        }
        if (bid == 0) g_off[N_NODES] = run;  // total edges
    }
    __syncthreads();
    int idx = blockIdx.x * SCAN_BLK + tid;
    if (idx < N_NODES) {
        int d = g_deg_i[idx];
        int excl = base_s + g_off[idx] - d;
        g_off[idx] = excl;
        g_cursor[idx] = excl;
        g_norm[idx] = rsqrtf(fmaxf((float)d, 1.0f));
    }
}

// Fill CSR edge list: packed (norm[src], src) per slot (absolute cursor).
__global__ void fill_kernel(const int* __restrict__ src,
                            const int* __restrict__ dst) {
    int e = blockIdx.x * blockDim.x + threadIdx.x;
    if (e < N_EDGES) {
        int s = src[e];
        unsigned long long p =
            ((unsigned long long)__float_as_uint(g_norm[s]) << 32) |
            (unsigned int)s;
        int pos = atomicAdd(&g_cursor[dst[e]], 1);
        g_epack[pos] = p;
    }
}

// ---------------------------------------------------------------------------
// Fused layer: aggregate 128 node rows into smem, then GEMM + bias (+relu).
//   out[n,:] = act( [ norm[n] * sum_e h[src_e,:]*norm[src_e] ] @ W + b )
// Block: 512 threads. smem: W (64KB) + H tile (64KB) = 128KB.
// Aggregation: warp w handles rows w*8..w*8+7; lanes cooperatively load 32
// packed (src,norm) pairs coalesced, shfl-broadcast, 4 independent LDG.128.
// GEMM: 8x4 register tile, LDS.128 A, packed fma.rn.f32x2.
// ---------------------------------------------------------------------------
template <bool LAYER1>
__global__ __launch_bounds__(512) void fused_layer_kernel(
    const float4* __restrict__ hin, const float* __restrict__ W,
    const float* __restrict__ bias, float* __restrict__ outp) {
    extern __shared__ float smem[];
    float* sW = smem;           // [128][128]
    float* sH = smem + D * D;   // [128][128]

    int tid  = threadIdx.x;
    int lane = tid & 31;
    int wid  = tid >> 5;        // 0..15
    int row0 = blockIdx.x * 128;

    const float4* __restrict__ h =
        LAYER1 ? hin : reinterpret_cast<const float4*>(g_h1);

    // Load W tile (coalesced float4)
    #pragma unroll 4
    for (int i = tid; i < D * D / 4; i += 512)
        reinterpret_cast<float4*>(sW)[i] =
            reinterpret_cast<const float4*>(W)[i];

    // Aggregate 8 rows per warp directly into sH
    #pragma unroll 1
    for (int r8 = 0; r8 < 8; r8++) {
        int rloc = wid * 8 + r8;
        int node = row0 + rloc;
        float4 acc = make_float4(0.f, 0.f, 0.f, 0.f);
        if (node < N_NODES) {
            int beg = g_off[node];
            int end = g_off[node + 1];
            for (int base = beg; base < end; base += 32) {
                int n = end - base;
                if (n > 32) n = 32;
                unsigned long long p = 0ull;
                if (lane < n) p = __ldg(&g_epack[base + lane]);  // coalesced
                int j = 0;
                for (; j + 4 <= n; j += 4) {
                    unsigned long long p0 = __shfl_sync(0xFFFFFFFFu, p, j);
                    unsigned long long p1 = __shfl_sync(0xFFFFFFFFu, p, j + 1);
                    unsigned long long p2 = __shfl_sync(0xFFFFFFFFu, p, j + 2);
                    unsigned long long p3 = __shfl_sync(0xFFFFFFFFu, p, j + 3);
                    int s0 = (int)(unsigned int)p0;
                    int s1 = (int)(unsigned int)p1;
                    int s2 = (int)(unsigned int)p2;
                    int s3 = (int)(unsigned int)p3;
                    float m0 = __uint_as_float((unsigned int)(p0 >> 32));
                    float m1 = __uint_as_float((unsigned int)(p1 >> 32));
                    float m2 = __uint_as_float((unsigned int)(p2 >> 32));
                    float m3 = __uint_as_float((unsigned int)(p3 >> 32));
                    float4 v0 = h[s0 * 32 + lane];
                    float4 v1 = h[s1 * 32 + lane];
                    float4 v2 = h[s2 * 32 + lane];
                    float4 v3 = h[s3 * 32 + lane];
                    acc.x += v0.x * m0; acc.y += v0.y * m0; acc.z += v0.z * m0; acc.w += v0.w * m0;
                    acc.x += v1.x * m1; acc.y += v1.y * m1; acc.z += v1.z * m1; acc.w += v1.w * m1;
                    acc.x += v2.x * m2; acc.y += v2.y * m2; acc.z += v2.z * m2; acc.w += v2.w * m2;
                    acc.x += v3.x * m3; acc.y += v3.y * m3; acc.z += v3.z * m3; acc.w += v3.w * m3;
                }
                for (; j < n; j++) {
                    unsigned long long p0 = __shfl_sync(0xFFFFFFFFu, p, j);
                    int s0 = (int)(unsigned int)p0;
                    float m0 = __uint_as_float((unsigned int)(p0 >> 32));
                    float4 v0 = h[s0 * 32 + lane];
                    acc.x += v0.x * m0; acc.y += v0.y * m0; acc.z += v0.z * m0; acc.w += v0.w * m0;
                }
            float dn = g_norm[node];
            acc.x *= dn; acc.y *= dn; acc.z *= dn; acc.w *= dn;
            }
        }
        reinterpret_cast<float4*>(&sH[rloc * D])[lane] = acc;
    }
    __syncthreads();

    // GEMM: 8x4 register tile per thread
    int tx = tid & 31;   // cols [tx*4, tx*4+4)
    int ty = tid >> 5;   // rows [ty*8, ty*8+8)

    unsigned long long acc[8][2];
    #pragma unroll
    for (int r = 0; r < 8; r++) { acc[r][0] = 0ull; acc[r][1] = 0ull; }

    for (int k = 0; k < D; k += 4) {
        ulonglong2 b0 = reinterpret_cast<const ulonglong2*>(&sW[(k + 0) * D])[tx];
        ulonglong2 b1 = reinterpret_cast<const ulonglong2*>(&sW[(k + 1) * D])[tx];
        ulonglong2 b2 = reinterpret_cast<const ulonglong2*>(&sW[(k + 2) * D])[tx];
        ulonglong2 b3 = reinterpret_cast<const ulonglong2*>(&sW[(k + 3) * D])[tx];
        #pragma unroll
        for (int r = 0; r < 8; r++) {
            float4 a4 = *reinterpret_cast<const float4*>(
                &sH[(ty * 8 + r) * D + k]);
            unsigned long long a2;
            asm("mov.b64 %0, {%1, %1};" : "=l"(a2) : "f"(a4.x));
            asm("fma.rn.f32x2 %0, %1, %2, %0;" : "+l"(acc[r][0]) : "l"(a2), "l"(b0.x));
            asm("fma.rn.f32x2 %0, %1, %2, %0;" : "+l"(acc[r][1]) : "l"(a2), "l"(b0.y));
            asm("mov.b64 %0, {%1, %1};" : "=l"(a2) : "f"(a4.y));
            asm("fma.rn.f32x2 %0, %1, %2, %0;" : "+l"(acc[r][0]) : "l"(a2), "l"(b1.x));
            asm("fma.rn.f32x2 %0, %1, %2, %0;" : "+l"(acc[r][1]) : "l"(a2), "l"(b1.y));
            asm("mov.b64 %0, {%1, %1};" : "=l"(a2) : "f"(a4.z));
            asm("fma.rn.f32x2 %0, %1, %2, %0;" : "+l"(acc[r][0]) : "l"(a2), "l"(b2.x));
            asm("fma.rn.f32x2 %0, %1, %2, %0;" : "+l"(acc[r][1]) : "l"(a2), "l"(b2.y));
            asm("mov.b64 %0, {%1, %1};" : "=l"(a2) : "f"(a4.w));
            asm("fma.rn.f32x2 %0, %1, %2, %0;" : "+l"(acc[r][0]) : "l"(a2), "l"(b3.x));
            asm("fma.rn.f32x2 %0, %1, %2, %0;" : "+l"(acc[r][1]) : "l"(a2), "l"(b3.y));
        }
    }

    float4 bb = reinterpret_cast<const float4*>(bias)[tx];
    #pragma unroll
    for (int r = 0; r < 8; r++) {
        int node = row0 + ty * 8 + r;
        if (node < N_NODES) {
            float4 o;
            asm("mov.b64 {%0, %1}, %2;" : "=f"(o.x), "=f"(o.y) : "l"(acc[r][0]));
            asm("mov.b64 {%0, %1}, %2;" : "=f"(o.z), "=f"(o.w) : "l"(acc[r][1]));
            o.x += bb.x; o.y += bb.y; o.z += bb.z; o.w += bb.w;
            if (LAYER1) {
                o.x = fmaxf(o.x, 0.f); o.y = fmaxf(o.y, 0.f);
                o.z = fmaxf(o.z, 0.f); o.w = fmaxf(o.w, 0.f);
            }
            float* dst = LAYER1 ? g_h1 : outp;
            reinterpret_cast<float4*>(dst)[node * 32 + tx] = o;
        }
    }
}

// ---------------------------------------------------------------------------
// Launch
// ---------------------------------------------------------------------------
extern "C" void kernel_launch(void* const* d_in, const int* in_sizes, int n_in,
                              void* d_out, int out_size) {
    const float* features = (const float*)d_in[0];
    const int*   src      = (const int*)d_in[1];
    const int*   dst      = (const int*)d_in[2];
    const float* W0       = (const float*)d_in[3];
    const float* b0       = (const float*)d_in[4];
    const float* W1       = (const float*)d_in[5];
    const float* b1       = (const float*)d_in[6];
    float* out = (float*)d_out;

    const int SMEM_FUSED = (D * D + 128 * D) * sizeof(float);  // 128 KB
    cudaFuncSetAttribute(fused_layer_kernel<true>,
                         cudaFuncAttributeMaxDynamicSharedMemorySize, SMEM_FUSED);
    cudaFuncSetAttribute(fused_layer_kernel<false>,
                         cudaFuncAttributeMaxDynamicSharedMemorySize, SMEM_FUSED);

    const int nodesBlocks = (N_NODES + 255) / 256;
    const int edgeBlocks  = (N_EDGES + 255) / 256;
    const int layerBlocks = (N_NODES + 127) / 128;

    // CSR build (5 launches)
    zero_kernel<<<nodesBlocks, 256>>>();
    hist_kernel<<<edgeBlocks, 256>>>(dst);
    scanA_kernel<<<NB, SCAN_BLK>>>();
    scanC_kernel<<<NB, SCAN_BLK>>>();
    fill_kernel<<<edgeBlocks, 256>>>(src, dst);

    // Fused layers (2 launches)
    fused_layer_kernel<true><<<layerBlocks, 512, SMEM_FUSED>>>(
        (const float4*)features, W0, b0, nullptr);
    fused_layer_kernel<false><<<layerBlocks, 512, SMEM_FUSED>>>(
        nullptr, W1, b1, out);
}

// round 6
// speedup vs baseline: 1.0520x; 1.0520x over previous
#include <cuda_runtime.h>
#include <cuda_bf16.h>
#include <cstdint>

#define N_NODES 50000
#define N_EDGES 600000
#define D 128
#define SCAN_BLK 1024
#define NB ((N_NODES + SCAN_BLK - 1) / SCAN_BLK)   // 49

// ---------------------------------------------------------------------------
// Scratch (device globals: allocation-free, graph-capturable)
// ---------------------------------------------------------------------------
__device__ int                g_deg_i[N_NODES];
__device__ int                g_cursor[N_NODES];
__device__ int                g_off[N_NODES + 1];
__device__ volatile int       g_flag[NB];    // 0=none, 1=aggregate, 2=prefix
__device__ volatile int       g_aggv[NB];
__device__ volatile int       g_prefv[NB];
__device__ unsigned long long g_epack[N_EDGES];  // (norm_bits<<32)|src, CSR order
__device__ float              g_norm[N_NODES];
__device__ float              g_agg[N_NODES * D];
__device__ float              g_h1[N_NODES * D];

// ---------------------------------------------------------------------------
// zero: degree counters + lookback flags (must reset every replay)
// ---------------------------------------------------------------------------
__global__ void zero_kernel() {
    int i = blockIdx.x * blockDim.x + threadIdx.x;
    if (i < N_NODES) g_deg_i[i] = 0;
    if (i < NB) g_flag[i] = 0;
}

__global__ void hist_kernel(const int* __restrict__ dst) {
    int i = blockIdx.x * blockDim.x + threadIdx.x;
    if (i < N_EDGES) atomicAdd(&g_deg_i[dst[i]], 1);
}

__device__ __forceinline__ int warp_incl_scan(int x, int lane) {
    #pragma unroll
    for (int ofs = 1; ofs < 32; ofs <<= 1) {
        int t = __shfl_up_sync(0xFFFFFFFFu, x, ofs);
        if (lane >= ofs) x += t;
    }
    return x;
}

// Single-pass decoupled-lookback scan: exclusive offsets + cursor + norm.
// Grid = NB (49) blocks <= #SMs, all resident -> spin-wait is safe.
__global__ __launch_bounds__(SCAN_BLK) void scan_kernel() {
    __shared__ int wsum[32];
    __shared__ int tot_s;
    __shared__ int base_s;
    int tid = threadIdx.x, lane = tid & 31, wid = tid >> 5;
    int bid = blockIdx.x;
    int idx = bid * SCAN_BLK + tid;

    int v = (idx < N_NODES) ? g_deg_i[idx] : 0;
    int incl = warp_incl_scan(v, lane);
    if (lane == 31) wsum[wid] = incl;
    __syncthreads();
    if (wid == 0) {
        int s = wsum[lane];
        int si = warp_incl_scan(s, lane);
        wsum[lane] = si - s;
    }
    __syncthreads();
    incl += wsum[wid];
    if (tid == SCAN_BLK - 1) tot_s = incl;
    __syncthreads();

    if (tid == 0) {
        int total = tot_s;
        if (bid == 0) {
            g_prefv[0] = total;
            __threadfence();
            g_flag[0] = 2;
            base_s = 0;
        } else {
            g_aggv[bid] = total;
            __threadfence();
            g_flag[bid] = 1;
            int run = 0;
            for (int i = bid - 1; i >= 0;) {
                int f;
                do { f = g_flag[i]; } while (f == 0);
                if (f == 2) { run += g_prefv[i]; break; }
                run += g_aggv[i];
                i--;
            }
            base_s = run;
            g_prefv[bid] = run + total;
            __threadfence();
            g_flag[bid] = 2;
        }
    }
    __syncthreads();

    int excl = base_s + incl - v;
    if (idx < N_NODES) {
        g_off[idx]    = excl;
        g_cursor[idx] = excl;
        g_norm[idx]   = rsqrtf(fmaxf((float)v, 1.0f));
    }
    if (bid == NB - 1 && tid == SCAN_BLK - 1)
        g_off[N_NODES] = base_s + tot_s;
}

// Fill CSR edge list: packed (norm[src], src) per slot (absolute cursor).
__global__ void fill_kernel(const int* __restrict__ src,
                            const int* __restrict__ dst) {
    int e = blockIdx.x * blockDim.x + threadIdx.x;
    if (e < N_EDGES) {
        int s = src[e];
        unsigned long long p =
            ((unsigned long long)__float_as_uint(g_norm[s]) << 32) |
            (unsigned int)s;
        int pos = atomicAdd(&g_cursor[dst[e]], 1);
        g_epack[pos] = p;
    }
}

// ---------------------------------------------------------------------------
// CSR aggregate: one warp per dst node. Lanes cooperatively load 32 packed
// (src,norm) pairs coalesced, shfl-broadcast; unroll-8 row gathers with dual
// accumulators (8 LDG.128 in flight, halved FFMA dep chain).
// ---------------------------------------------------------------------------
template <bool LAYER1>
__global__ __launch_bounds__(256) void aggregate_kernel(const float4* __restrict__ hin) {
    int warp = (blockIdx.x * blockDim.x + threadIdx.x) >> 5;
    int lane = threadIdx.x & 31;
    if (warp >= N_NODES) return;
    const float4* __restrict__ h =
        LAYER1 ? hin : reinterpret_cast<const float4*>(g_h1);

    int beg = g_off[warp];
    int end = g_off[warp + 1];

    float4 acc0 = make_float4(0.f, 0.f, 0.f, 0.f);
    float4 acc1 = make_float4(0.f, 0.f, 0.f, 0.f);

    for (int base = beg; base < end; base += 32) {
        int n = end - base;
        if (n > 32) n = 32;
        unsigned long long p = 0ull;
        if (lane < n) p = __ldg(&g_epack[base + lane]);  // coalesced
        int j = 0;
        for (; j + 8 <= n; j += 8) {
            unsigned long long p0 = __shfl_sync(0xFFFFFFFFu, p, j);
            unsigned long long p1 = __shfl_sync(0xFFFFFFFFu, p, j + 1);
            unsigned long long p2 = __shfl_sync(0xFFFFFFFFu, p, j + 2);
            unsigned long long p3 = __shfl_sync(0xFFFFFFFFu, p, j + 3);
            unsigned long long p4 = __shfl_sync(0xFFFFFFFFu, p, j + 4);
            unsigned long long p5 = __shfl_sync(0xFFFFFFFFu, p, j + 5);
            unsigned long long p6 = __shfl_sync(0xFFFFFFFFu, p, j + 6);
            unsigned long long p7 = __shfl_sync(0xFFFFFFFFu, p, j + 7);
            float4 v0 = h[(int)(unsigned int)p0 * 32 + lane];
            float4 v1 = h[(int)(unsigned int)p1 * 32 + lane];
            float4 v2 = h[(int)(unsigned int)p2 * 32 + lane];
            float4 v3 = h[(int)(unsigned int)p3 * 32 + lane];
            float4 v4 = h[(int)(unsigned int)p4 * 32 + lane];
            float4 v5 = h[(int)(unsigned int)p5 * 32 + lane];
            float4 v6 = h[(int)(unsigned int)p6 * 32 + lane];
            float4 v7 = h[(int)(unsigned int)p7 * 32 + lane];
            float m0 = __uint_as_float((unsigned int)(p0 >> 32));
            float m1 = __uint_as_float((unsigned int)(p1 >> 32));
            float m2 = __uint_as_float((unsigned int)(p2 >> 32));
            float m3 = __uint_as_float((unsigned int)(p3 >> 32));
            float m4 = __uint_as_float((unsigned int)(p4 >> 32));
            float m5 = __uint_as_float((unsigned int)(p5 >> 32));
            float m6 = __uint_as_float((unsigned int)(p6 >> 32));
            float m7 = __uint_as_float((unsigned int)(p7 >> 32));
            acc0.x += v0.x * m0; acc0.y += v0.y * m0; acc0.z += v0.z * m0; acc0.w += v0.w * m0;
            acc1.x += v1.x * m1; acc1.y += v1.y * m1; acc1.z += v1.z * m1; acc1.w += v1.w * m1;
            acc0.x += v2.x * m2; acc0.y += v2.y * m2; acc0.z += v2.z * m2; acc0.w += v2.w * m2;
            acc1.x += v3.x * m3; acc1.y += v3.y * m3; acc1.z += v3.z * m3; acc1.w += v3.w * m3;
            acc0.x += v4.x * m4; acc0.y += v4.y * m4; acc0.z += v4.z * m4; acc0.w += v4.w * m4;
            acc1.x += v5.x * m5; acc1.y += v5.y * m5; acc1.z += v5.z * m5; acc1.w += v5.w * m5;
            acc0.x += v6.x * m6; acc0.y += v6.y * m6; acc0.z += v6.z * m6; acc0.w += v6.w * m6;
            acc1.x += v7.x * m7; acc1.y += v7.y * m7; acc1.z += v7.z * m7; acc1.w += v7.w * m7;
        }
        for (; j + 2 <= n; j += 2) {
            unsigned long long p0 = __shfl_sync(0xFFFFFFFFu, p, j);
            unsigned long long p1 = __shfl_sync(0xFFFFFFFFu, p, j + 1);
            float4 v0 = h[(int)(unsigned int)p0 * 32 + lane];
            float4 v1 = h[(int)(unsigned int)p1 * 32 + lane];
            float m0 = __uint_as_float((unsigned int)(p0 >> 32));
            float m1 = __uint_as_float((unsigned int)(p1 >> 32));
            acc0.x += v0.x * m0; acc0.y += v0.y * m0; acc0.z += v0.z * m0; acc0.w += v0.w * m0;
            acc1.x += v1.x * m1; acc1.y += v1.y * m1; acc1.z += v1.z * m1; acc1.w += v1.w * m1;
        }
        if (j < n) {
            unsigned long long p0 = __shfl_sync(0xFFFFFFFFu, p, j);
            float4 v0 = h[(int)(unsigned int)p0 * 32 + lane];
            float m0 = __uint_as_float((unsigned int)(p0 >> 32));
            acc0.x += v0.x * m0; acc0.y += v0.y * m0; acc0.z += v0.z * m0; acc0.w += v0.w * m0;
        }
    }
    float dn = g_norm[warp];
    float4 o;
    o.x = (acc0.x + acc1.x) * dn;
    o.y = (acc0.y + acc1.y) * dn;
    o.z = (acc0.z + acc1.z) * dn;
    o.w = (acc0.w + acc1.w) * dn;
    reinterpret_cast<float4*>(g_agg)[warp * 32 + lane] = o;
}

// ---------------------------------------------------------------------------
// Epilogue GEMM (proven round-4 config): out = relu?(agg @ W + b)
// 128x128 tile, 512 threads, LDS.128 A, packed fma.rn.f32x2.
// ---------------------------------------------------------------------------
template <bool LAYER1>
__global__ __launch_bounds__(512) void epilogue_kernel(
    const float* __restrict__ W, const float* __restrict__ bias,
    float* __restrict__ outp) {
    extern __shared__ float smem[];
    float* sW = smem;           // [128][128]
    float* sH = smem + D * D;   // [128][128]

    int tid  = threadIdx.x;
    int row0 = blockIdx.x * 128;

    #pragma unroll 4
    for (int i = tid; i < D * D / 4; i += 512)
        reinterpret_cast<float4*>(sW)[i] =
            reinterpret_cast<const float4*>(W)[i];

    for (int i = tid; i < 128 * (D / 4); i += 512) {
        int r  = i >> 5;
        int c4 = i & 31;
        int node = row0 + r;
        float4 v = make_float4(0.f, 0.f, 0.f, 0.f);
        if (node < N_NODES)
            v = reinterpret_cast<const float4*>(g_agg)[node * 32 + c4];
        reinterpret_cast<float4*>(sH)[i] = v;
    }
    __syncthreads();

    int tx = tid & 31;
    int ty = tid >> 5;

    unsigned long long acc[8][2];
    #pragma unroll
    for (int r = 0; r < 8; r++) { acc[r][0] = 0ull; acc[r][1] = 0ull; }

    for (int k = 0; k < D; k += 4) {
        ulonglong2 b0 = reinterpret_cast<const ulonglong2*>(&sW[(k + 0) * D])[tx];
        ulonglong2 b1 = reinterpret_cast<const ulonglong2*>(&sW[(k + 1) * D])[tx];
        ulonglong2 b2 = reinterpret_cast<const ulonglong2*>(&sW[(k + 2) * D])[tx];
        ulonglong2 b3 = reinterpret_cast<const ulonglong2*>(&sW[(k + 3) * D])[tx];
        #pragma unroll
        for (int r = 0; r < 8; r++) {
            float4 a4 = *reinterpret_cast<const float4*>(
                &sH[(ty * 8 + r) * D + k]);
            unsigned long long a2;
            asm("mov.b64 %0, {%1, %1};" : "=l"(a2) : "f"(a4.x));
            asm("fma.rn.f32x2 %0, %1, %2, %0;" : "+l"(acc[r][0]) : "l"(a2), "l"(b0.x));
            asm("fma.rn.f32x2 %0, %1, %2, %0;" : "+l"(acc[r][1]) : "l"(a2), "l"(b0.y));
            asm("mov.b64 %0, {%1, %1};" : "=l"(a2) : "f"(a4.y));
            asm("fma.rn.f32x2 %0, %1, %2, %0;" : "+l"(acc[r][0]) : "l"(a2), "l"(b1.x));
            asm("fma.rn.f32x2 %0, %1, %2, %0;" : "+l"(acc[r][1]) : "l"(a2), "l"(b1.y));
            asm("mov.b64 %0, {%1, %1};" : "=l"(a2) : "f"(a4.z));
            asm("fma.rn.f32x2 %0, %1, %2, %0;" : "+l"(acc[r][0]) : "l"(a2), "l"(b2.x));
            asm("fma.rn.f32x2 %0, %1, %2, %0;" : "+l"(acc[r][1]) : "l"(a2), "l"(b2.y));
            asm("mov.b64 %0, {%1, %1};" : "=l"(a2) : "f"(a4.w));
            asm("fma.rn.f32x2 %0, %1, %2, %0;" : "+l"(acc[r][0]) : "l"(a2), "l"(b3.x));
            asm("fma.rn.f32x2 %0, %1, %2, %0;" : "+l"(acc[r][1]) : "l"(a2), "l"(b3.y));
        }
    }

    float4 bb = reinterpret_cast<const float4*>(bias)[tx];
    #pragma unroll
    for (int r = 0; r < 8; r++) {
        int node = row0 + ty * 8 + r;
        if (node < N_NODES) {
            float4 o;
            asm("mov.b64 {%0, %1}, %2;" : "=f"(o.x), "=f"(o.y) : "l"(acc[r][0]));
            asm("mov.b64 {%0, %1}, %2;" : "=f"(o.z), "=f"(o.w) : "l"(acc[r][1]));
            o.x += bb.x; o.y += bb.y; o.z += bb.z; o.w += bb.w;
            if (LAYER1) {
                o.x = fmaxf(o.x, 0.f); o.y = fmaxf(o.y, 0.f);
                o.z = fmaxf(o.z, 0.f); o.w = fmaxf(o.w, 0.f);
            }
            float* dst = LAYER1 ? g_h1 : outp;
            reinterpret_cast<float4*>(dst)[node * 32 + tx] = o;
        }
    }
}

// ---------------------------------------------------------------------------
// Launch
// ---------------------------------------------------------------------------
extern "C" void kernel_launch(void* const* d_in, const int* in_sizes, int n_in,
                              void* d_out, int out_size) {
    const float* features = (const float*)d_in[0];
    const int*   src      = (const int*)d_in[1];
    const int*   dst      = (const int*)d_in[2];
    const float* W0       = (const float*)d_in[3];
    const float* b0       = (const float*)d_in[4];
    const float* W1       = (const float*)d_in[5];
    const float* b1       = (const float*)d_in[6];
    float* out = (float*)d_out;

    const int SMEM_EPI = (D * D + 128 * D) * sizeof(float);  // 128 KB
    cudaFuncSetAttribute(epilogue_kernel<true>,
                         cudaFuncAttributeMaxDynamicSharedMemorySize, SMEM_EPI);
    cudaFuncSetAttribute(epilogue_kernel<false>,
                         cudaFuncAttributeMaxDynamicSharedMemorySize, SMEM_EPI);

    const int nodesBlocks = (N_NODES + 255) / 256;
    const int edgeBlocks  = (N_EDGES + 255) / 256;
    const int aggBlocks   = (N_NODES + 7) / 8;
    const int epiBlocks   = (N_NODES + 127) / 128;

    // CSR build (4 launches)
    zero_kernel<<<nodesBlocks, 256>>>();
    hist_kernel<<<edgeBlocks, 256>>>(dst);
    scan_kernel<<<NB, SCAN_BLK>>>();
    fill_kernel<<<edgeBlocks, 256>>>(src, dst);

    // Layer 1
    aggregate_kernel<true><<<aggBlocks, 256>>>((const float4*)features);
    epilogue_kernel<true><<<epiBlocks, 512, SMEM_EPI>>>(W0, b0, nullptr);

    // Layer 2
    aggregate_kernel<false><<<aggBlocks, 256>>>(nullptr);
    epilogue_kernel<false><<<epiBlocks, 512, SMEM_EPI>>>(W1, b1, out);
}

// round 7
// speedup vs baseline: 1.1327x; 1.0768x over previous
#include <cuda_runtime.h>
#include <cuda_bf16.h>
#include <cstdint>

#define N_NODES 50000
#define N_EDGES 600000
#define D 128
#define SCAN_BLK 1024
#define NB ((N_NODES + SCAN_BLK - 1) / SCAN_BLK)   // 49

// ---------------------------------------------------------------------------
// Scratch (device globals: allocation-free, graph-capturable)
// ---------------------------------------------------------------------------
__device__ int                g_deg_i[N_NODES];
__device__ int                g_cursor[N_NODES];
__device__ int                g_off[N_NODES];     // exclusive offset (per-block base via atomic)
__device__ int                g_counter;          // scan base allocator
__device__ unsigned long long g_epack[N_EDGES];   // (norm_bits<<32)|src, CSR order
__device__ float              g_norm[N_NODES];
__device__ float              g_agg[N_NODES * D];
__device__ float              g_h1[N_NODES * D];

// ---------------------------------------------------------------------------
// zero: degree counters + scan base counter
// ---------------------------------------------------------------------------
__global__ void zero_kernel() {
    int i = blockIdx.x * blockDim.x + threadIdx.x;
    if (i < N_NODES) g_deg_i[i] = 0;
    if (i == 0) g_counter = 0;
}

// Histogram: 4 edges per thread (int4 load) for 4 independent atomic chains.
__global__ void hist_kernel(const int4* __restrict__ dst4) {
    int i = blockIdx.x * blockDim.x + threadIdx.x;
    if (i < N_EDGES / 4) {
        int4 d = __ldg(&dst4[i]);
        atomicAdd(&g_deg_i[d.x], 1);
        atomicAdd(&g_deg_i[d.y], 1);
        atomicAdd(&g_deg_i[d.z], 1);
        atomicAdd(&g_deg_i[d.w], 1);
    }
}

__device__ __forceinline__ int warp_incl_scan(int x, int lane) {
    #pragma unroll
    for (int ofs = 1; ofs < 32; ofs <<= 1) {
        int t = __shfl_up_sync(0xFFFFFFFFu, x, ofs);
        if (lane >= ofs) x += t;
    }
    return x;
}

// Scan: block-local exclusive prefix; block base from one atomicAdd.
// Offsets are NOT monotone across blocks — consumers use beg + deg as end.
__global__ __launch_bounds__(SCAN_BLK) void scan_kernel() {
    __shared__ int wsum[32];
    __shared__ int base_s;
    int tid = threadIdx.x, lane = tid & 31, wid = tid >> 5;
    int idx = blockIdx.x * SCAN_BLK + tid;

    int v = (idx < N_NODES) ? g_deg_i[idx] : 0;
    int incl = warp_incl_scan(v, lane);
    if (lane == 31) wsum[wid] = incl;
    __syncthreads();
    if (wid == 0) {
        int s = wsum[lane];
        int si = warp_incl_scan(s, lane);
        wsum[lane] = si - s;
    }
    __syncthreads();
    incl += wsum[wid];
    if (tid == SCAN_BLK - 1) base_s = atomicAdd(&g_counter, incl);
    __syncthreads();

    if (idx < N_NODES) {
        int excl = base_s + incl - v;
        g_off[idx]    = excl;
        g_cursor[idx] = excl;
        g_norm[idx]   = rsqrtf(fmaxf((float)v, 1.0f));
    }
}

// Fill CSR edge list: 4 edges per thread, packed (norm[src], src) per slot.
__global__ void fill_kernel(const int4* __restrict__ src4,
                            const int4* __restrict__ dst4) {
    int i = blockIdx.x * blockDim.x + threadIdx.x;
    if (i < N_EDGES / 4) {
        int4 s = __ldg(&src4[i]);
        int4 d = __ldg(&dst4[i]);
        unsigned long long p0 =
            ((unsigned long long)__float_as_uint(g_norm[s.x]) << 32) | (unsigned int)s.x;
        unsigned long long p1 =
            ((unsigned long long)__float_as_uint(g_norm[s.y]) << 32) | (unsigned int)s.y;
        unsigned long long p2 =
            ((unsigned long long)__float_as_uint(g_norm[s.z]) << 32) | (unsigned int)s.z;
        unsigned long long p3 =
            ((unsigned long long)__float_as_uint(g_norm[s.w]) << 32) | (unsigned int)s.w;
        int q0 = atomicAdd(&g_cursor[d.x], 1);
        int q1 = atomicAdd(&g_cursor[d.y], 1);
        int q2 = atomicAdd(&g_cursor[d.z], 1);
        int q3 = atomicAdd(&g_cursor[d.w], 1);
        g_epack[q0] = p0;
        g_epack[q1] = p1;
        g_epack[q2] = p2;
        g_epack[q3] = p3;
    }
}

// ---------------------------------------------------------------------------
// CSR aggregate (round-4 proven structure): one warp per dst node.
// Lanes cooperatively load 32 packed (src,norm) pairs coalesced, broadcast via
// shfl -> row-gather addresses register-resident, 4 independent LDG.128.
// ---------------------------------------------------------------------------
template <bool LAYER1>
__global__ __launch_bounds__(256) void aggregate_kernel(const float4* __restrict__ hin) {
    int warp = (blockIdx.x * blockDim.x + threadIdx.x) >> 5;
    int lane = threadIdx.x & 31;
    if (warp >= N_NODES) return;
    const float4* __restrict__ h =
        LAYER1 ? hin : reinterpret_cast<const float4*>(g_h1);

    int beg = g_off[warp];
    int end = beg + __ldg(&g_deg_i[warp]);

    float4 acc = make_float4(0.f, 0.f, 0.f, 0.f);

    for (int base = beg; base < end; base += 32) {
        int n = end - base;
        if (n > 32) n = 32;
        unsigned long long p = 0ull;
        if (lane < n) p = __ldg(&g_epack[base + lane]);  // coalesced
        int j = 0;
        for (; j + 4 <= n; j += 4) {
            unsigned long long p0 = __shfl_sync(0xFFFFFFFFu, p, j);
            unsigned long long p1 = __shfl_sync(0xFFFFFFFFu, p, j + 1);
            unsigned long long p2 = __shfl_sync(0xFFFFFFFFu, p, j + 2);
            unsigned long long p3 = __shfl_sync(0xFFFFFFFFu, p, j + 3);
            float4 v0 = h[(int)(unsigned int)p0 * 32 + lane];
            float4 v1 = h[(int)(unsigned int)p1 * 32 + lane];
            float4 v2 = h[(int)(unsigned int)p2 * 32 + lane];
            float4 v3 = h[(int)(unsigned int)p3 * 32 + lane];
            float m0 = __uint_as_float((unsigned int)(p0 >> 32));
            float m1 = __uint_as_float((unsigned int)(p1 >> 32));
            float m2 = __uint_as_float((unsigned int)(p2 >> 32));
            float m3 = __uint_as_float((unsigned int)(p3 >> 32));
            acc.x += v0.x * m0; acc.y += v0.y * m0; acc.z += v0.z * m0; acc.w += v0.w * m0;
            acc.x += v1.x * m1; acc.y += v1.y * m1; acc.z += v1.z * m1; acc.w += v1.w * m1;
            acc.x += v2.x * m2; acc.y += v2.y * m2; acc.z += v2.z * m2; acc.w += v2.w * m2;
            acc.x += v3.x * m3; acc.y += v3.y * m3; acc.z += v3.z * m3; acc.w += v3.w * m3;
        }
        for (; j < n; j++) {
            unsigned long long p0 = __shfl_sync(0xFFFFFFFFu, p, j);
            float4 v0 = h[(int)(unsigned int)p0 * 32 + lane];
            float m0 = __uint_as_float((unsigned int)(p0 >> 32));
            acc.x += v0.x * m0; acc.y += v0.y * m0; acc.z += v0.z * m0; acc.w += v0.w * m0;
        }
    }
    float dn = g_norm[warp];
    acc.x *= dn; acc.y *= dn; acc.z *= dn; acc.w *= dn;
    reinterpret_cast<float4*>(g_agg)[warp * 32 + lane] = acc;
}

// ---------------------------------------------------------------------------
// Epilogue GEMM (proven round-4 config): out = relu?(agg @ W + b)
// 128x128 tile, 512 threads, LDS.128 A, packed fma.rn.f32x2.
// ---------------------------------------------------------------------------
template <bool LAYER1>
__global__ __launch_bounds__(512) void epilogue_kernel(
    const float* __restrict__ W, const float* __restrict__ bias,
    float* __restrict__ outp) {
    extern __shared__ float smem[];
    float* sW = smem;           // [128][128]
    float* sH = smem + D * D;   // [128][128]

    int tid  = threadIdx.x;
    int row0 = blockIdx.x * 128;

    #pragma unroll 4
    for (int i = tid; i < D * D / 4; i += 512)
        reinterpret_cast<float4*>(sW)[i] =
            reinterpret_cast<const float4*>(W)[i];

    for (int i = tid; i < 128 * (D / 4); i += 512) {
        int r  = i >> 5;
        int c4 = i & 31;
        int node = row0 + r;
        float4 v = make_float4(0.f, 0.f, 0.f, 0.f);
        if (node < N_NODES)
            v = reinterpret_cast<const float4*>(g_agg)[node * 32 + c4];
        reinterpret_cast<float4*>(sH)[i] = v;
    }
    __syncthreads();

    int tx = tid & 31;
    int ty = tid >> 5;

    unsigned long long acc[8][2];
    #pragma unroll
    for (int r = 0; r < 8; r++) { acc[r][0] = 0ull; acc[r][1] = 0ull; }

    for (int k = 0; k < D; k += 4) {
        ulonglong2 b0 = reinterpret_cast<const ulonglong2*>(&sW[(k + 0) * D])[tx];
        ulonglong2 b1 = reinterpret_cast<const ulonglong2*>(&sW[(k + 1) * D])[tx];
        ulonglong2 b2 = reinterpret_cast<const ulonglong2*>(&sW[(k + 2) * D])[tx];
        ulonglong2 b3 = reinterpret_cast<const ulonglong2*>(&sW[(k + 3) * D])[tx];
        #pragma unroll
        for (int r = 0; r < 8; r++) {
            float4 a4 = *reinterpret_cast<const float4*>(
                &sH[(ty * 8 + r) * D + k]);
            unsigned long long a2;
            asm("mov.b64 %0, {%1, %1};" : "=l"(a2) : "f"(a4.x));
            asm("fma.rn.f32x2 %0, %1, %2, %0;" : "+l"(acc[r][0]) : "l"(a2), "l"(b0.x));
            asm("fma.rn.f32x2 %0, %1, %2, %0;" : "+l"(acc[r][1]) : "l"(a2), "l"(b0.y));
            asm("mov.b64 %0, {%1, %1};" : "=l"(a2) : "f"(a4.y));
            asm("fma.rn.f32x2 %0, %1, %2, %0;" : "+l"(acc[r][0]) : "l"(a2), "l"(b1.x));
            asm("fma.rn.f32x2 %0, %1, %2, %0;" : "+l"(acc[r][1]) : "l"(a2), "l"(b1.y));
            asm("mov.b64 %0, {%1, %1};" : "=l"(a2) : "f"(a4.z));
            asm("fma.rn.f32x2 %0, %1, %2, %0;" : "+l"(acc[r][0]) : "l"(a2), "l"(b2.x));
            asm("fma.rn.f32x2 %0, %1, %2, %0;" : "+l"(acc[r][1]) : "l"(a2), "l"(b2.y));
            asm("mov.b64 %0, {%1, %1};" : "=l"(a2) : "f"(a4.w));
            asm("fma.rn.f32x2 %0, %1, %2, %0;" : "+l"(acc[r][0]) : "l"(a2), "l"(b3.x));
            asm("fma.rn.f32x2 %0, %1, %2, %0;" : "+l"(acc[r][1]) : "l"(a2), "l"(b3.y));
        }
    }

    float4 bb = reinterpret_cast<const float4*>(bias)[tx];
    #pragma unroll
    for (int r = 0; r < 8; r++) {
        int node = row0 + ty * 8 + r;
        if (node < N_NODES) {
            float4 o;
            asm("mov.b64 {%0, %1}, %2;" : "=f"(o.x), "=f"(o.y) : "l"(acc[r][0]));
            asm("mov.b64 {%0, %1}, %2;" : "=f"(o.z), "=f"(o.w) : "l"(acc[r][1]));
            o.x += bb.x; o.y += bb.y; o.z += bb.z; o.w += bb.w;
            if (LAYER1) {
                o.x = fmaxf(o.x, 0.f); o.y = fmaxf(o.y, 0.f);
                o.z = fmaxf(o.z, 0.f); o.w = fmaxf(o.w, 0.f);
            }
            float* dst = LAYER1 ? g_h1 : outp;
            reinterpret_cast<float4*>(dst)[node * 32 + tx] = o;
        }
    }
}

// ---------------------------------------------------------------------------
// Launch
// ---------------------------------------------------------------------------
extern "C" void kernel_launch(void* const* d_in, const int* in_sizes, int n_in,
                              void* d_out, int out_size) {
    const float* features = (const float*)d_in[0];
    const int*   src      = (const int*)d_in[1];
    const int*   dst      = (const int*)d_in[2];
    const float* W0       = (const float*)d_in[3];
    const float* b0       = (const float*)d_in[4];
    const float* W1       = (const float*)d_in[5];
    const float* b1       = (const float*)d_in[6];
    float* out = (float*)d_out;

    const int SMEM_EPI = (D * D + 128 * D) * sizeof(float);  // 128 KB
    cudaFuncSetAttribute(epilogue_kernel<true>,
                         cudaFuncAttributeMaxDynamicSharedMemorySize, SMEM_EPI);
    cudaFuncSetAttribute(epilogue_kernel<false>,
                         cudaFuncAttributeMaxDynamicSharedMemorySize, SMEM_EPI);

    const int nodesBlocks = (N_NODES + 255) / 256;
    const int edge4Blocks = (N_EDGES / 4 + 255) / 256;
    const int aggBlocks   = (N_NODES + 7) / 8;
    const int epiBlocks   = (N_NODES + 127) / 128;

    // CSR build (4 launches)
    zero_kernel<<<nodesBlocks, 256>>>();
    hist_kernel<<<edge4Blocks, 256>>>((const int4*)dst);
    scan_kernel<<<NB, SCAN_BLK>>>();
    fill_kernel<<<edge4Blocks, 256>>>((const int4*)src, (const int4*)dst);

    // Layer 1
    aggregate_kernel<true><<<aggBlocks, 256>>>((const float4*)features);
    epilogue_kernel<true><<<epiBlocks, 512, SMEM_EPI>>>(W0, b0, nullptr);

    // Layer 2
    aggregate_kernel<false><<<aggBlocks, 256>>>(nullptr);
    epilogue_kernel<false><<<epiBlocks, 512, SMEM_EPI>>>(W1, b1, out);
}

// round 9
// speedup vs baseline: 1.1582x; 1.0225x over previous
#include <cuda_runtime.h>
#include <cuda_bf16.h>
#include <cstdint>

#define N_NODES 50000
#define N_EDGES 600000
#define D 128
#define SCAN_BLK 1024
#define NB ((N_NODES + SCAN_BLK - 1) / SCAN_BLK)   // 49
#define S 132   // smem row stride (floats) to avoid bank conflicts

// ---------------------------------------------------------------------------
// Scratch (device globals: allocation-free, graph-capturable)
// ---------------------------------------------------------------------------
__device__ int                g_deg_i[N_NODES];
__device__ int                g_cursor[N_NODES];
__device__ int                g_off[N_NODES];
__device__ int                g_counter;
__device__ unsigned long long g_epack[N_EDGES];   // (norm_bits<<32)|src, CSR order
__device__ float              g_norm[N_NODES];
__device__ float              g_agg[N_NODES * D];
__device__ float              g_h1[N_NODES * D];

// ---------------------------------------------------------------------------
// CSR build (proven round-7 kernels)
// ---------------------------------------------------------------------------
__global__ void zero_kernel() {
    int i = blockIdx.x * blockDim.x + threadIdx.x;
    if (i < N_NODES) g_deg_i[i] = 0;
    if (i == 0) g_counter = 0;
}

__global__ void hist_kernel(const int4* __restrict__ dst4) {
    int i = blockIdx.x * blockDim.x + threadIdx.x;
    if (i < N_EDGES / 4) {
        int4 d = __ldg(&dst4[i]);
        atomicAdd(&g_deg_i[d.x], 1);
        atomicAdd(&g_deg_i[d.y], 1);
        atomicAdd(&g_deg_i[d.z], 1);
        atomicAdd(&g_deg_i[d.w], 1);
    }
}

__device__ __forceinline__ int warp_incl_scan(int x, int lane) {
    #pragma unroll
    for (int ofs = 1; ofs < 32; ofs <<= 1) {
        int t = __shfl_up_sync(0xFFFFFFFFu, x, ofs);
        if (lane >= ofs) x += t;
    }
    return x;
}

__global__ __launch_bounds__(SCAN_BLK) void scan_kernel() {
    __shared__ int wsum[32];
    __shared__ int base_s;
    int tid = threadIdx.x, lane = tid & 31, wid = tid >> 5;
    int idx = blockIdx.x * SCAN_BLK + tid;

    int v = (idx < N_NODES) ? g_deg_i[idx] : 0;
    int incl = warp_incl_scan(v, lane);
    if (lane == 31) wsum[wid] = incl;
    __syncthreads();
    if (wid == 0) {
        int s = wsum[lane];
        int si = warp_incl_scan(s, lane);
        wsum[lane] = si - s;
    }
    __syncthreads();
    incl += wsum[wid];
    if (tid == SCAN_BLK - 1) base_s = atomicAdd(&g_counter, incl);
    __syncthreads();

    if (idx < N_NODES) {
        int excl = base_s + incl - v;
        g_off[idx]    = excl;
        g_cursor[idx] = excl;
        g_norm[idx]   = rsqrtf(fmaxf((float)v, 1.0f));
    }
}

__global__ void fill_kernel(const int4* __restrict__ src4,
                            const int4* __restrict__ dst4) {
    int i = blockIdx.x * blockDim.x + threadIdx.x;
    if (i < N_EDGES / 4) {
        int4 s = __ldg(&src4[i]);
        int4 d = __ldg(&dst4[i]);
        unsigned long long p0 =
            ((unsigned long long)__float_as_uint(g_norm[s.x]) << 32) | (unsigned int)s.x;
        unsigned long long p1 =
            ((unsigned long long)__float_as_uint(g_norm[s.y]) << 32) | (unsigned int)s.y;
        unsigned long long p2 =
            ((unsigned long long)__float_as_uint(g_norm[s.z]) << 32) | (unsigned int)s.z;
        unsigned long long p3 =
            ((unsigned long long)__float_as_uint(g_norm[s.w]) << 32) | (unsigned int)s.w;
        int q0 = atomicAdd(&g_cursor[d.x], 1);
        int q1 = atomicAdd(&g_cursor[d.y], 1);
        int q2 = atomicAdd(&g_cursor[d.z], 1);
        int q3 = atomicAdd(&g_cursor[d.w], 1);
        g_epack[q0] = p0;
        g_epack[q1] = p1;
        g_epack[q2] = p2;
        g_epack[q3] = p3;
    }
}

// ---------------------------------------------------------------------------
// CSR aggregate (proven round-4/7 structure): one warp per dst node.
// ---------------------------------------------------------------------------
template <bool LAYER1>
__global__ __launch_bounds__(256) void aggregate_kernel(const float4* __restrict__ hin) {
    int warp = (blockIdx.x * blockDim.x + threadIdx.x) >> 5;
    int lane = threadIdx.x & 31;
    if (warp >= N_NODES) return;
    const float4* __restrict__ h =
        LAYER1 ? hin : reinterpret_cast<const float4*>(g_h1);

    int beg = g_off[warp];
    int end = beg + __ldg(&g_deg_i[warp]);

    float4 acc = make_float4(0.f, 0.f, 0.f, 0.f);

    for (int base = beg; base < end; base += 32) {
        int n = end - base;
        if (n > 32) n = 32;
        unsigned long long p = 0ull;
        if (lane < n) p = __ldg(&g_epack[base + lane]);
        int j = 0;
        for (; j + 4 <= n; j += 4) {
            unsigned long long p0 = __shfl_sync(0xFFFFFFFFu, p, j);
            unsigned long long p1 = __shfl_sync(0xFFFFFFFFu, p, j + 1);
            unsigned long long p2 = __shfl_sync(0xFFFFFFFFu, p, j + 2);
            unsigned long long p3 = __shfl_sync(0xFFFFFFFFu, p, j + 3);
            float4 v0 = h[(int)(unsigned int)p0 * 32 + lane];
            float4 v1 = h[(int)(unsigned int)p1 * 32 + lane];
            float4 v2 = h[(int)(unsigned int)p2 * 32 + lane];
            float4 v3 = h[(int)(unsigned int)p3 * 32 + lane];
            float m0 = __uint_as_float((unsigned int)(p0 >> 32));
            float m1 = __uint_as_float((unsigned int)(p1 >> 32));
            float m2 = __uint_as_float((unsigned int)(p2 >> 32));
            float m3 = __uint_as_float((unsigned int)(p3 >> 32));
            acc.x += v0.x * m0; acc.y += v0.y * m0; acc.z += v0.z * m0; acc.w += v0.w * m0;
            acc.x += v1.x * m1; acc.y += v1.y * m1; acc.z += v1.z * m1; acc.w += v1.w * m1;
            acc.x += v2.x * m2; acc.y += v2.y * m2; acc.z += v2.z * m2; acc.w += v2.w * m2;
            acc.x += v3.x * m3; acc.y += v3.y * m3; acc.z += v3.z * m3; acc.w += v3.w * m3;
        }
        for (; j < n; j++) {
            unsigned long long p0 = __shfl_sync(0xFFFFFFFFu, p, j);
            float4 v0 = h[(int)(unsigned int)p0 * 32 + lane];
            float m0 = __uint_as_float((unsigned int)(p0 >> 32));
            acc.x += v0.x * m0; acc.y += v0.y * m0; acc.z += v0.z * m0; acc.w += v0.w * m0;
        }
    }
    float dn = g_norm[warp];
    acc.x *= dn; acc.y *= dn; acc.z *= dn; acc.w *= dn;
    reinterpret_cast<float4*>(g_agg)[warp * 32 + lane] = acc;
}

// ---------------------------------------------------------------------------
// TF32 helpers
// ---------------------------------------------------------------------------
__device__ __forceinline__ unsigned f2tf32(float x) {
    unsigned r;
    asm("cvt.rna.tf32.f32 %0, %1;" : "=r"(r) : "f"(x));
    return r;
}

__device__ __forceinline__ void mma_tf32(float* d, const unsigned* a,
                                         const unsigned* b) {
    asm("mma.sync.aligned.m16n8k8.row.col.f32.tf32.tf32.f32 "
        "{%0,%1,%2,%3}, {%4,%5,%6,%7}, {%8,%9}, {%0,%1,%2,%3};"
        : "+f"(d[0]), "+f"(d[1]), "+f"(d[2]), "+f"(d[3])
        : "r"(a[0]), "r"(a[1]), "r"(a[2]), "r"(a[3]), "r"(b[0]), "r"(b[1]));
}

// ---------------------------------------------------------------------------
// Epilogue GEMM on tensor cores (tf32): out = relu?(agg @ W + b)
// Block: 128 rows x 128 cols, 256 threads (8 warps as 4x2).
// Warp computes 32 rows x 64 cols via m16n8k8 tf32 mma, fp32 accumulate.
// CORRECT PTX fragment layout for m16n8k8 tf32 (g=lane>>2, t=lane&3):
//   A: a0=(g, t)  a1=(g+8, t)  a2=(g, t+4)  a3=(g+8, t+4)     [row-major m16k8]
//   B: b0=(k=t, n=g)  b1=(k=t+4, n=g)                          [col-major k8n8]
//   C: c0=(g, 2t) c1=(g, 2t+1) c2=(g+8, 2t) c3=(g+8, 2t+1)
// smem stride S=132: fragment addresses map to bank (g*4+t)%32 -> conflict-free.
// ---------------------------------------------------------------------------
template <bool LAYER1>
__global__ __launch_bounds__(256) void epilogue_kernel(
    const float* __restrict__ W, const float* __restrict__ bias,
    float* __restrict__ outp) {
    extern __shared__ float smem[];
    float* sWt = smem;           // [128 n][S]  (k contiguous)
    float* sH  = smem + D * S;   // [128 m][S]  (k contiguous)

    int tid  = threadIdx.x;
    int lane = tid & 31;
    int warp = tid >> 5;
    int warpM = warp & 3;        // 0..3 -> 32-row slab
    int warpN = warp >> 2;       // 0..1 -> 64-col slab
    int g = lane >> 2;           // groupID 0..7
    int t = lane & 3;            // thread-in-group 0..3
    int row0 = blockIdx.x * 128;

    // Load W [k][n] -> sWt[n][k], tf32-converted. Coalesced float4 reads.
    for (int i = tid; i < D * D / 4; i += 256) {
        int k  = i >> 5;          // 32 float4 per k-row
        int n0 = (i & 31) * 4;
        float4 w = __ldg(&reinterpret_cast<const float4*>(W)[i]);
        sWt[(n0 + 0) * S + k] = __uint_as_float(f2tf32(w.x));
        sWt[(n0 + 1) * S + k] = __uint_as_float(f2tf32(w.y));
        sWt[(n0 + 2) * S + k] = __uint_as_float(f2tf32(w.z));
        sWt[(n0 + 3) * S + k] = __uint_as_float(f2tf32(w.w));
    }

    // Load agg tile -> sH[m][k], tf32-converted. Zero-pad rows beyond N_NODES.
    for (int i = tid; i < 128 * (D / 4); i += 256) {
        int r  = i >> 5;
        int c4 = i & 31;
        int node = row0 + r;
        float4 v = make_float4(0.f, 0.f, 0.f, 0.f);
        if (node < N_NODES)
            v = reinterpret_cast<const float4*>(g_agg)[node * 32 + c4];
        float* p = &sH[r * S + c4 * 4];
        p[0] = __uint_as_float(f2tf32(v.x));
        p[1] = __uint_as_float(f2tf32(v.y));
        p[2] = __uint_as_float(f2tf32(v.z));
        p[3] = __uint_as_float(f2tf32(v.w));
    }
    __syncthreads();

    float acc[2][8][4];
    #pragma unroll
    for (int mi = 0; mi < 2; mi++)
        #pragma unroll
        for (int ni = 0; ni < 8; ni++)
            #pragma unroll
            for (int c = 0; c < 4; c++) acc[mi][ni][c] = 0.f;

    #pragma unroll 4
    for (int kt = 0; kt < 16; kt++) {
        int k0 = kt * 8;
        unsigned a[2][4];
        #pragma unroll
        for (int mi = 0; mi < 2; mi++) {
            int R = warpM * 32 + mi * 16;
            a[mi][0] = __float_as_uint(sH[(R + g)     * S + k0 + t]);
            a[mi][1] = __float_as_uint(sH[(R + g + 8) * S + k0 + t]);
            a[mi][2] = __float_as_uint(sH[(R + g)     * S + k0 + t + 4]);
            a[mi][3] = __float_as_uint(sH[(R + g + 8) * S + k0 + t + 4]);
        }
        #pragma unroll
        for (int ni = 0; ni < 8; ni++) {
            int C = warpN * 64 + ni * 8;
            unsigned b[2];
            b[0] = __float_as_uint(sWt[(C + g) * S + k0 + t]);
            b[1] = __float_as_uint(sWt[(C + g) * S + k0 + t + 4]);
            mma_tf32(acc[0][ni], a[0], b);
            mma_tf32(acc[1][ni], a[1], b);
        }
    }

    // Write out: bias + optional relu, float2 stores (cols 2t, 2t+1).
    float* dst = LAYER1 ? g_h1 : outp;
    #pragma unroll
    for (int ni = 0; ni < 8; ni++) {
        int c = warpN * 64 + ni * 8 + 2 * t;
        float2 bb = *reinterpret_cast<const float2*>(&bias[c]);
        #pragma unroll
        for (int mi = 0; mi < 2; mi++) {
            int r1 = row0 + warpM * 32 + mi * 16 + g;
            int r2 = r1 + 8;
            float2 o1 = make_float2(acc[mi][ni][0] + bb.x,
                                    acc[mi][ni][1] + bb.y);
            float2 o2 = make_float2(acc[mi][ni][2] + bb.x,
                                    acc[mi][ni][3] + bb.y);
            if (LAYER1) {
                o1.x = fmaxf(o1.x, 0.f); o1.y = fmaxf(o1.y, 0.f);
                o2.x = fmaxf(o2.x, 0.f); o2.y = fmaxf(o2.y, 0.f);
            }
            if (r1 < N_NODES)
                *reinterpret_cast<float2*>(&dst[r1 * D + c]) = o1;
            if (r2 < N_NODES)
                *reinterpret_cast<float2*>(&dst[r2 * D + c]) = o2;
        }
    }
}

// ---------------------------------------------------------------------------
// Launch
// ---------------------------------------------------------------------------
extern "C" void kernel_launch(void* const* d_in, const int* in_sizes, int n_in,
                              void* d_out, int out_size) {
    const float* features = (const float*)d_in[0];
    const int*   src      = (const int*)d_in[1];
    const int*   dst      = (const int*)d_in[2];
    const float* W0       = (const float*)d_in[3];
    const float* b0       = (const float*)d_in[4];
    const float* W1       = (const float*)d_in[5];
    const float* b1       = (const float*)d_in[6];
    float* out = (float*)d_out;

    const int SMEM_EPI = 2 * D * S * sizeof(float);  // 135168 B
    cudaFuncSetAttribute(epilogue_kernel<true>,
                         cudaFuncAttributeMaxDynamicSharedMemorySize, SMEM_EPI);
    cudaFuncSetAttribute(epilogue_kernel<false>,
                         cudaFuncAttributeMaxDynamicSharedMemorySize, SMEM_EPI);

    const int nodesBlocks = (N_NODES + 255) / 256;
    const int edge4Blocks = (N_EDGES / 4 + 255) / 256;
    const int aggBlocks   = (N_NODES + 7) / 8;
    const int epiBlocks   = (N_NODES + 127) / 128;

    // CSR build (4 launches)
    zero_kernel<<<nodesBlocks, 256>>>();
    hist_kernel<<<edge4Blocks, 256>>>((const int4*)dst);
    scan_kernel<<<NB, SCAN_BLK>>>();
    fill_kernel<<<edge4Blocks, 256>>>((const int4*)src, (const int4*)dst);

    // Layer 1
    aggregate_kernel<true><<<aggBlocks, 256>>>((const float4*)features);
    epilogue_kernel<true><<<epiBlocks, 256, SMEM_EPI>>>(W0, b0, nullptr);

    // Layer 2
    aggregate_kernel<false><<<aggBlocks, 256>>>(nullptr);
    epilogue_kernel<false><<<epiBlocks, 256, SMEM_EPI>>>(W1, b1, out);
}

// round 10
// speedup vs baseline: 1.1732x; 1.0130x over previous
#include <cuda_runtime.h>
#include <cuda_bf16.h>
#include <cstdint>

#define N_NODES 50000
#define N_EDGES 600000
#define D 128
#define SCAN_BLK 1024
#define NB ((N_NODES + SCAN_BLK - 1) / SCAN_BLK)   // 49
#define S 132   // smem row stride (floats) to avoid bank conflicts

// ---------------------------------------------------------------------------
// Scratch (device globals: allocation-free, graph-capturable)
// ---------------------------------------------------------------------------
__device__ int   g_deg_i[N_NODES];
__device__ int   g_cursor[N_NODES];
__device__ int   g_off[N_NODES];
__device__ int   g_counter;
__device__ int   g_eidx[N_EDGES];     // src index per edge, CSR order
__device__ float g_norm[N_NODES];
__device__ float g_hs[N_NODES * D];   // norm-prescaled layer input (layer 1)
__device__ float g_agg[N_NODES * D];
__device__ float g_h1[N_NODES * D];   // norm-prescaled relu output (layer 2 in)

// ---------------------------------------------------------------------------
// CSR build
// ---------------------------------------------------------------------------
__global__ void zero_kernel() {
    int i = blockIdx.x * blockDim.x + threadIdx.x;
    if (i < N_NODES) g_deg_i[i] = 0;
    if (i == 0) g_counter = 0;
}

__global__ void hist_kernel(const int4* __restrict__ dst4) {
    int i = blockIdx.x * blockDim.x + threadIdx.x;
    if (i < N_EDGES / 4) {
        int4 d = __ldg(&dst4[i]);
        atomicAdd(&g_deg_i[d.x], 1);
        atomicAdd(&g_deg_i[d.y], 1);
        atomicAdd(&g_deg_i[d.z], 1);
        atomicAdd(&g_deg_i[d.w], 1);
    }
}

__device__ __forceinline__ int warp_incl_scan(int x, int lane) {
    #pragma unroll
    for (int ofs = 1; ofs < 32; ofs <<= 1) {
        int t = __shfl_up_sync(0xFFFFFFFFu, x, ofs);
        if (lane >= ofs) x += t;
    }
    return x;
}

__global__ __launch_bounds__(SCAN_BLK) void scan_kernel() {
    __shared__ int wsum[32];
    __shared__ int base_s;
    int tid = threadIdx.x, lane = tid & 31, wid = tid >> 5;
    int idx = blockIdx.x * SCAN_BLK + tid;

    int v = (idx < N_NODES) ? g_deg_i[idx] : 0;
    int incl = warp_incl_scan(v, lane);
    if (lane == 31) wsum[wid] = incl;
    __syncthreads();
    if (wid == 0) {
        int s = wsum[lane];
        int si = warp_incl_scan(s, lane);
        wsum[lane] = si - s;
    }
    __syncthreads();
    incl += wsum[wid];
    if (tid == SCAN_BLK - 1) base_s = atomicAdd(&g_counter, incl);
    __syncthreads();

    if (idx < N_NODES) {
        int excl = base_s + incl - v;
        g_off[idx]    = excl;
        g_cursor[idx] = excl;
        g_norm[idx]   = rsqrtf(fmaxf((float)v, 1.0f));
    }
}

// Fill CSR edge list: src index only (no norm gather — prefolded into rows).
__global__ void fill_kernel(const int4* __restrict__ src4,
                            const int4* __restrict__ dst4) {
    int i = blockIdx.x * blockDim.x + threadIdx.x;
    if (i < N_EDGES / 4) {
        int4 s = __ldg(&src4[i]);
        int4 d = __ldg(&dst4[i]);
        int q0 = atomicAdd(&g_cursor[d.x], 1);
        int q1 = atomicAdd(&g_cursor[d.y], 1);
        int q2 = atomicAdd(&g_cursor[d.z], 1);
        int q3 = atomicAdd(&g_cursor[d.w], 1);
        g_eidx[q0] = s.x;
        g_eidx[q1] = s.y;
        g_eidx[q2] = s.z;
        g_eidx[q3] = s.w;
    }
}

// Prescale features by node norm: hs = norm (.) features (coalesced float4).
__global__ void prescale_kernel(const float4* __restrict__ f) {
    int i = blockIdx.x * blockDim.x + threadIdx.x;
    if (i < N_NODES * (D / 4)) {
        float nm = g_norm[i >> 5];
        float4 v = __ldg(&f[i]);
        v.x *= nm; v.y *= nm; v.z *= nm; v.w *= nm;
        reinterpret_cast<float4*>(g_hs)[i] = v;
    }
}

// ---------------------------------------------------------------------------
// CSR aggregate: one warp per dst node (proven shape). Inputs are already
// norm-prescaled, so the inner loop is pure gather + tree add.
//   agg[n,:] = norm[n] * sum_e hs[src_e,:]
// ---------------------------------------------------------------------------
template <bool LAYER1>
__global__ __launch_bounds__(256) void aggregate_kernel() {
    int warp = (blockIdx.x * blockDim.x + threadIdx.x) >> 5;
    int lane = threadIdx.x & 31;
    if (warp >= N_NODES) return;
    const float4* __restrict__ h = reinterpret_cast<const float4*>(
        LAYER1 ? g_hs : g_h1);

    int beg = g_off[warp];
    int end = beg + __ldg(&g_deg_i[warp]);

    float4 acc = make_float4(0.f, 0.f, 0.f, 0.f);

    for (int base = beg; base < end; base += 32) {
        int n = end - base;
        if (n > 32) n = 32;
        int idx = 0;
        if (lane < n) idx = __ldg(&g_eidx[base + lane]);  // coalesced
        int j = 0;
        for (; j + 4 <= n; j += 4) {
            int s0 = __shfl_sync(0xFFFFFFFFu, idx, j);
            int s1 = __shfl_sync(0xFFFFFFFFu, idx, j + 1);
            int s2 = __shfl_sync(0xFFFFFFFFu, idx, j + 2);
            int s3 = __shfl_sync(0xFFFFFFFFu, idx, j + 3);
            float4 v0 = h[s0 * 32 + lane];
            float4 v1 = h[s1 * 32 + lane];
            float4 v2 = h[s2 * 32 + lane];
            float4 v3 = h[s3 * 32 + lane];
            // tree add: shortens the dependence chain on acc
            float4 t0, t1;
            t0.x = v0.x + v1.x; t0.y = v0.y + v1.y;
            t0.z = v0.z + v1.z; t0.w = v0.w + v1.w;
            t1.x = v2.x + v3.x; t1.y = v2.y + v3.y;
            t1.z = v2.z + v3.z; t1.w = v2.w + v3.w;
            acc.x += t0.x + t1.x; acc.y += t0.y + t1.y;
            acc.z += t0.z + t1.z; acc.w += t0.w + t1.w;
        }
        for (; j < n; j++) {
            int s0 = __shfl_sync(0xFFFFFFFFu, idx, j);
            float4 v0 = h[s0 * 32 + lane];
            acc.x += v0.x; acc.y += v0.y; acc.z += v0.z; acc.w += v0.w;
        }
    }
    float dn = g_norm[warp];
    acc.x *= dn; acc.y *= dn; acc.z *= dn; acc.w *= dn;
    reinterpret_cast<float4*>(g_agg)[warp * 32 + lane] = acc;
}

// ---------------------------------------------------------------------------
// TF32 helpers
// ---------------------------------------------------------------------------
__device__ __forceinline__ unsigned f2tf32(float x) {
    unsigned r;
    asm("cvt.rna.tf32.f32 %0, %1;" : "=r"(r) : "f"(x));
    return r;
}

__device__ __forceinline__ void mma_tf32(float* d, const unsigned* a,
                                         const unsigned* b) {
    asm("mma.sync.aligned.m16n8k8.row.col.f32.tf32.tf32.f32 "
        "{%0,%1,%2,%3}, {%4,%5,%6,%7}, {%8,%9}, {%0,%1,%2,%3};"
        : "+f"(d[0]), "+f"(d[1]), "+f"(d[2]), "+f"(d[3])
        : "r"(a[0]), "r"(a[1]), "r"(a[2]), "r"(a[3]), "r"(b[0]), "r"(b[1]));
}

// ---------------------------------------------------------------------------
// Epilogue GEMM on tensor cores (tf32, proven round-9 layout):
//   LAYER1: h1 = norm (.) relu(agg @ W + b)   (prescale for next layer)
//   else:   out = agg @ W + b
// ---------------------------------------------------------------------------
template <bool LAYER1>
__global__ __launch_bounds__(256) void epilogue_kernel(
    const float* __restrict__ W, const float* __restrict__ bias,
    float* __restrict__ outp) {
    extern __shared__ float smem[];
    float* sWt = smem;           // [128 n][S]  (k contiguous)
    float* sH  = smem + D * S;   // [128 m][S]  (k contiguous)

    int tid  = threadIdx.x;
    int lane = tid & 31;
    int warp = tid >> 5;
    int warpM = warp & 3;
    int warpN = warp >> 2;
    int g = lane >> 2;
    int t = lane & 3;
    int row0 = blockIdx.x * 128;

    for (int i = tid; i < D * D / 4; i += 256) {
        int k  = i >> 5;
        int n0 = (i & 31) * 4;
        float4 w = __ldg(&reinterpret_cast<const float4*>(W)[i]);
        sWt[(n0 + 0) * S + k] = __uint_as_float(f2tf32(w.x));
        sWt[(n0 + 1) * S + k] = __uint_as_float(f2tf32(w.y));
        sWt[(n0 + 2) * S + k] = __uint_as_float(f2tf32(w.z));
        sWt[(n0 + 3) * S + k] = __uint_as_float(f2tf32(w.w));
    }

    for (int i = tid; i < 128 * (D / 4); i += 256) {
        int r  = i >> 5;
        int c4 = i & 31;
        int node = row0 + r;
        float4 v = make_float4(0.f, 0.f, 0.f, 0.f);
        if (node < N_NODES)
            v = reinterpret_cast<const float4*>(g_agg)[node * 32 + c4];
        float* p = &sH[r * S + c4 * 4];
        p[0] = __uint_as_float(f2tf32(v.x));
        p[1] = __uint_as_float(f2tf32(v.y));
        p[2] = __uint_as_float(f2tf32(v.z));
        p[3] = __uint_as_float(f2tf32(v.w));
    }
    __syncthreads();

    float acc[2][8][4];
    #pragma unroll
    for (int mi = 0; mi < 2; mi++)
        #pragma unroll
        for (int ni = 0; ni < 8; ni++)
            #pragma unroll
            for (int c = 0; c < 4; c++) acc[mi][ni][c] = 0.f;

    #pragma unroll 4
    for (int kt = 0; kt < 16; kt++) {
        int k0 = kt * 8;
        unsigned a[2][4];
        #pragma unroll
        for (int mi = 0; mi < 2; mi++) {
            int R = warpM * 32 + mi * 16;
            a[mi][0] = __float_as_uint(sH[(R + g)     * S + k0 + t]);
            a[mi][1] = __float_as_uint(sH[(R + g + 8) * S + k0 + t]);
            a[mi][2] = __float_as_uint(sH[(R + g)     * S + k0 + t + 4]);
            a[mi][3] = __float_as_uint(sH[(R + g + 8) * S + k0 + t + 4]);
        }
        #pragma unroll
        for (int ni = 0; ni < 8; ni++) {
            int C = warpN * 64 + ni * 8;
            unsigned b[2];
            b[0] = __float_as_uint(sWt[(C + g) * S + k0 + t]);
            b[1] = __float_as_uint(sWt[(C + g) * S + k0 + t + 4]);
            mma_tf32(acc[0][ni], a[0], b);
            mma_tf32(acc[1][ni], a[1], b);
        }
    }

    // Per-row norms for LAYER1 prescale (rows depend only on mi)
    float nmA[2] = {1.f, 1.f}, nmB[2] = {1.f, 1.f};
    if (LAYER1) {
        #pragma unroll
        for (int mi = 0; mi < 2; mi++) {
            int r1 = row0 + warpM * 32 + mi * 16 + g;
            int r2 = r1 + 8;
            nmA[mi] = (r1 < N_NODES) ? g_norm[r1] : 0.f;
            nmB[mi] = (r2 < N_NODES) ? g_norm[r2] : 0.f;
        }
    }

    float* dst = LAYER1 ? g_h1 : outp;
    #pragma unroll
    for (int ni = 0; ni < 8; ni++) {
        int c = warpN * 64 + ni * 8 + 2 * t;
        float2 bb = *reinterpret_cast<const float2*>(&bias[c]);
        #pragma unroll
        for (int mi = 0; mi < 2; mi++) {
            int r1 = row0 + warpM * 32 + mi * 16 + g;
            int r2 = r1 + 8;
            float2 o1 = make_float2(acc[mi][ni][0] + bb.x,
                                    acc[mi][ni][1] + bb.y);
            float2 o2 = make_float2(acc[mi][ni][2] + bb.x,
                                    acc[mi][ni][3] + bb.y);
            if (LAYER1) {
                o1.x = fmaxf(o1.x, 0.f) * nmA[mi];
                o1.y = fmaxf(o1.y, 0.f) * nmA[mi];
                o2.x = fmaxf(o2.x, 0.f) * nmB[mi];
                o2.y = fmaxf(o2.y, 0.f) * nmB[mi];
            }
            if (r1 < N_NODES)
                *reinterpret_cast<float2*>(&dst[r1 * D + c]) = o1;
            if (r2 < N_NODES)
                *reinterpret_cast<float2*>(&dst[r2 * D + c]) = o2;
        }
    }
}

// ---------------------------------------------------------------------------
// Launch
// ---------------------------------------------------------------------------
extern "C" void kernel_launch(void* const* d_in, const int* in_sizes, int n_in,
                              void* d_out, int out_size) {
    const float* features = (const float*)d_in[0];
    const int*   src      = (const int*)d_in[1];
    const int*   dst      = (const int*)d_in[2];
    const float* W0       = (const float*)d_in[3];
    const float* b0       = (const float*)d_in[4];
    const float* W1       = (const float*)d_in[5];
    const float* b1       = (const float*)d_in[6];
    float* out = (float*)d_out;

    const int SMEM_EPI = 2 * D * S * sizeof(float);  // 135168 B
    cudaFuncSetAttribute(epilogue_kernel<true>,
                         cudaFuncAttributeMaxDynamicSharedMemorySize, SMEM_EPI);
    cudaFuncSetAttribute(epilogue_kernel<false>,
                         cudaFuncAttributeMaxDynamicSharedMemorySize, SMEM_EPI);

    const int nodesBlocks = (N_NODES + 255) / 256;
    const int edge4Blocks = (N_EDGES / 4 + 255) / 256;
    const int vecBlocks   = (N_NODES * (D / 4) + 255) / 256;
    const int aggBlocks   = (N_NODES + 7) / 8;
    const int epiBlocks   = (N_NODES + 127) / 128;

    // CSR build + prescale (5 launches)
    zero_kernel<<<nodesBlocks, 256>>>();
    hist_kernel<<<edge4Blocks, 256>>>((const int4*)dst);
    scan_kernel<<<NB, SCAN_BLK>>>();
    fill_kernel<<<edge4Blocks, 256>>>((const int4*)src, (const int4*)dst);
    prescale_kernel<<<vecBlocks, 256>>>((const float4*)features);

    // Layer 1
    aggregate_kernel<true><<<aggBlocks, 256>>>();
    epilogue_kernel<true><<<epiBlocks, 256, SMEM_EPI>>>(W0, b0, nullptr);

    // Layer 2
    aggregate_kernel<false><<<aggBlocks, 256>>>();
    epilogue_kernel<false><<<epiBlocks, 256, SMEM_EPI>>>(W1, b1, out);
}

// round 11
// speedup vs baseline: 1.2885x; 1.0982x over previous
#include <cuda_runtime.h>
#include <cuda_fp16.h>
#include <cstdint>

#define N_NODES 50000
#define N_EDGES 600000
#define D 128
#define SCAN_BLK 1024
#define NB ((N_NODES + SCAN_BLK - 1) / SCAN_BLK)   // 49
#define S 132   // smem row stride (floats) to avoid bank conflicts

// ---------------------------------------------------------------------------
// Scratch (device globals: allocation-free, graph-capturable)
// ---------------------------------------------------------------------------
__device__ int    g_deg_i[N_NODES];
__device__ int    g_cursor[N_NODES];
__device__ int    g_off[N_NODES];
__device__ int    g_counter;
__device__ int    g_eidx[N_EDGES];      // src index per edge, CSR order
__device__ float  g_norm[N_NODES];
__device__ __half g_hs[N_NODES * D];    // norm-prescaled layer-1 input (fp16)
__device__ __half g_h1[N_NODES * D];    // norm-prescaled relu output (fp16)
__device__ float  g_agg[N_NODES * D];   // aggregate (fp32)

// ---------------------------------------------------------------------------
// CSR build (proven kernels, frozen)
// ---------------------------------------------------------------------------
__global__ void zero_kernel() {
    int i = blockIdx.x * blockDim.x + threadIdx.x;
    if (i < N_NODES) g_deg_i[i] = 0;
    if (i == 0) g_counter = 0;
}

__global__ void hist_kernel(const int4* __restrict__ dst4) {
    int i = blockIdx.x * blockDim.x + threadIdx.x;
    if (i < N_EDGES / 4) {
        int4 d = __ldg(&dst4[i]);
        atomicAdd(&g_deg_i[d.x], 1);
        atomicAdd(&g_deg_i[d.y], 1);
        atomicAdd(&g_deg_i[d.z], 1);
        atomicAdd(&g_deg_i[d.w], 1);
    }
}

__device__ __forceinline__ int warp_incl_scan(int x, int lane) {
    #pragma unroll
    for (int ofs = 1; ofs < 32; ofs <<= 1) {
        int t = __shfl_up_sync(0xFFFFFFFFu, x, ofs);
        if (lane >= ofs) x += t;
    }
    return x;
}

__global__ __launch_bounds__(SCAN_BLK) void scan_kernel() {
    __shared__ int wsum[32];
    __shared__ int base_s;
    int tid = threadIdx.x, lane = tid & 31, wid = tid >> 5;
    int idx = blockIdx.x * SCAN_BLK + tid;

    int v = (idx < N_NODES) ? g_deg_i[idx] : 0;
    int incl = warp_incl_scan(v, lane);
    if (lane == 31) wsum[wid] = incl;
    __syncthreads();
    if (wid == 0) {
        int s = wsum[lane];
        int si = warp_incl_scan(s, lane);
        wsum[lane] = si - s;
    }
    __syncthreads();
    incl += wsum[wid];
    if (tid == SCAN_BLK - 1) base_s = atomicAdd(&g_counter, incl);
    __syncthreads();

    if (idx < N_NODES) {
        int excl = base_s + incl - v;
        g_off[idx]    = excl;
        g_cursor[idx] = excl;
        g_norm[idx]   = rsqrtf(fmaxf((float)v, 1.0f));
    }
}

__global__ void fill_kernel(const int4* __restrict__ src4,
                            const int4* __restrict__ dst4) {
    int i = blockIdx.x * blockDim.x + threadIdx.x;
    if (i < N_EDGES / 4) {
        int4 s = __ldg(&src4[i]);
        int4 d = __ldg(&dst4[i]);
        int q0 = atomicAdd(&g_cursor[d.x], 1);
        int q1 = atomicAdd(&g_cursor[d.y], 1);
        int q2 = atomicAdd(&g_cursor[d.z], 1);
        int q3 = atomicAdd(&g_cursor[d.w], 1);
        g_eidx[q0] = s.x;
        g_eidx[q1] = s.y;
        g_eidx[q2] = s.z;
        g_eidx[q3] = s.w;
    }
}

// Prescale features by node norm -> fp16: hs = half(norm (.) features)
__global__ void prescale_kernel(const float4* __restrict__ f) {
    int i = blockIdx.x * blockDim.x + threadIdx.x;
    if (i < N_NODES * (D / 4)) {
        float nm = g_norm[i >> 5];
        float4 v = __ldg(&f[i]);
        half2 a = __floats2half2_rn(v.x * nm, v.y * nm);
        half2 b = __floats2half2_rn(v.z * nm, v.w * nm);
        uint2 u;
        u.x = *reinterpret_cast<unsigned*>(&a);
        u.y = *reinterpret_cast<unsigned*>(&b);
        reinterpret_cast<uint2*>(g_hs)[i] = u;
    }
}

// ---------------------------------------------------------------------------
// CSR aggregate: one warp per dst node (proven shape), fp16 rows (LDG.64),
// fp32 accumulation.  agg[n,:] = norm[n] * sum_e hs[src_e,:]
// Lane owns columns 4*lane .. 4*lane+3 (one uint2 = 4 halfs per row).
// ---------------------------------------------------------------------------
template <bool LAYER1>
__global__ __launch_bounds__(256) void aggregate_kernel() {
    int warp = (blockIdx.x * blockDim.x + threadIdx.x) >> 5;
    int lane = threadIdx.x & 31;
    if (warp >= N_NODES) return;
    const uint2* __restrict__ h = reinterpret_cast<const uint2*>(
        LAYER1 ? g_hs : g_h1);   // 32 uint2 per row

    int beg = g_off[warp];
    int end = beg + __ldg(&g_deg_i[warp]);

    float4 acc = make_float4(0.f, 0.f, 0.f, 0.f);

    for (int base = beg; base < end; base += 32) {
        int n = end - base;
        if (n > 32) n = 32;
        int idx = 0;
        if (lane < n) idx = __ldg(&g_eidx[base + lane]);  // coalesced
        int j = 0;
        for (; j + 4 <= n; j += 4) {
            int s0 = __shfl_sync(0xFFFFFFFFu, idx, j);
            int s1 = __shfl_sync(0xFFFFFFFFu, idx, j + 1);
            int s2 = __shfl_sync(0xFFFFFFFFu, idx, j + 2);
            int s3 = __shfl_sync(0xFFFFFFFFu, idx, j + 3);
            uint2 u0 = __ldg(&h[s0 * 32 + lane]);
            uint2 u1 = __ldg(&h[s1 * 32 + lane]);
            uint2 u2 = __ldg(&h[s2 * 32 + lane]);
            uint2 u3 = __ldg(&h[s3 * 32 + lane]);
            float2 a0 = __half22float2(*reinterpret_cast<half2*>(&u0.x));
            float2 b0 = __half22float2(*reinterpret_cast<half2*>(&u0.y));
            float2 a1 = __half22float2(*reinterpret_cast<half2*>(&u1.x));
            float2 b1 = __half22float2(*reinterpret_cast<half2*>(&u1.y));
            float2 a2 = __half22float2(*reinterpret_cast<half2*>(&u2.x));
            float2 b2 = __half22float2(*reinterpret_cast<half2*>(&u2.y));
            float2 a3 = __half22float2(*reinterpret_cast<half2*>(&u3.x));
            float2 b3 = __half22float2(*reinterpret_cast<half2*>(&u3.y));
            // tree add to shorten the acc dependence chain
            float tx0 = a0.x + a1.x, tx1 = a2.x + a3.x;
            float ty0 = a0.y + a1.y, ty1 = a2.y + a3.y;
            float tz0 = b0.x + b1.x, tz1 = b2.x + b3.x;
            float tw0 = b0.y + b1.y, tw1 = b2.y + b3.y;
            acc.x += tx0 + tx1;
            acc.y += ty0 + ty1;
            acc.z += tz0 + tz1;
            acc.w += tw0 + tw1;
        }
        for (; j < n; j++) {
            int s0 = __shfl_sync(0xFFFFFFFFu, idx, j);
            uint2 u0 = __ldg(&h[s0 * 32 + lane]);
            float2 a0 = __half22float2(*reinterpret_cast<half2*>(&u0.x));
            float2 b0 = __half22float2(*reinterpret_cast<half2*>(&u0.y));
            acc.x += a0.x; acc.y += a0.y; acc.z += b0.x; acc.w += b0.y;
        }
    }
    float dn = g_norm[warp];
    acc.x *= dn; acc.y *= dn; acc.z *= dn; acc.w *= dn;
    reinterpret_cast<float4*>(g_agg)[warp * 32 + lane] = acc;
}

// ---------------------------------------------------------------------------
// TF32 helpers
// ---------------------------------------------------------------------------
__device__ __forceinline__ unsigned f2tf32(float x) {
    unsigned r;
    asm("cvt.rna.tf32.f32 %0, %1;" : "=r"(r) : "f"(x));
    return r;
}

__device__ __forceinline__ void mma_tf32(float* d, const unsigned* a,
                                         const unsigned* b) {
    asm("mma.sync.aligned.m16n8k8.row.col.f32.tf32.tf32.f32 "
        "{%0,%1,%2,%3}, {%4,%5,%6,%7}, {%8,%9}, {%0,%1,%2,%3};"
        : "+f"(d[0]), "+f"(d[1]), "+f"(d[2]), "+f"(d[3])
        : "r"(a[0]), "r"(a[1]), "r"(a[2]), "r"(a[3]), "r"(b[0]), "r"(b[1]));
}

// ---------------------------------------------------------------------------
// Epilogue GEMM on tensor cores (tf32, proven round-9 layout):
//   LAYER1: h1 = half( norm (.) relu(agg @ W + b) )
//   else:   out = agg @ W + b   (fp32)
// ---------------------------------------------------------------------------
template <bool LAYER1>
__global__ __launch_bounds__(256) void epilogue_kernel(
    const float* __restrict__ W, const float* __restrict__ bias,
    float* __restrict__ outp) {
    extern __shared__ float smem[];
    float* sWt = smem;           // [128 n][S]  (k contiguous)
    float* sH  = smem + D * S;   // [128 m][S]  (k contiguous)

    int tid  = threadIdx.x;
    int lane = tid & 31;
    int warp = tid >> 5;
    int warpM = warp & 3;
    int warpN = warp >> 2;
    int g = lane >> 2;
    int t = lane & 3;
    int row0 = blockIdx.x * 128;

    for (int i = tid; i < D * D / 4; i += 256) {
        int k  = i >> 5;
        int n0 = (i & 31) * 4;
        float4 w = __ldg(&reinterpret_cast<const float4*>(W)[i]);
        sWt[(n0 + 0) * S + k] = __uint_as_float(f2tf32(w.x));
        sWt[(n0 + 1) * S + k] = __uint_as_float(f2tf32(w.y));
        sWt[(n0 + 2) * S + k] = __uint_as_float(f2tf32(w.z));
        sWt[(n0 + 3) * S + k] = __uint_as_float(f2tf32(w.w));
    }

    for (int i = tid; i < 128 * (D / 4); i += 256) {
        int r  = i >> 5;
        int c4 = i & 31;
        int node = row0 + r;
        float4 v = make_float4(0.f, 0.f, 0.f, 0.f);
        if (node < N_NODES)
            v = reinterpret_cast<const float4*>(g_agg)[node * 32 + c4];
        float* p = &sH[r * S + c4 * 4];
        p[0] = __uint_as_float(f2tf32(v.x));
        p[1] = __uint_as_float(f2tf32(v.y));
        p[2] = __uint_as_float(f2tf32(v.z));
        p[3] = __uint_as_float(f2tf32(v.w));
    }
    __syncthreads();

    float acc[2][8][4];
    #pragma unroll
    for (int mi = 0; mi < 2; mi++)
        #pragma unroll
        for (int ni = 0; ni < 8; ni++)
            #pragma unroll
            for (int c = 0; c < 4; c++) acc[mi][ni][c] = 0.f;

    #pragma unroll 4
    for (int kt = 0; kt < 16; kt++) {
        int k0 = kt * 8;
        unsigned a[2][4];
        #pragma unroll
        for (int mi = 0; mi < 2; mi++) {
            int R = warpM * 32 + mi * 16;
            a[mi][0] = __float_as_uint(sH[(R + g)     * S + k0 + t]);
            a[mi][1] = __float_as_uint(sH[(R + g + 8) * S + k0 + t]);
            a[mi][2] = __float_as_uint(sH[(R + g)     * S + k0 + t + 4]);
            a[mi][3] = __float_as_uint(sH[(R + g + 8) * S + k0 + t + 4]);
        }
        #pragma unroll
        for (int ni = 0; ni < 8; ni++) {
            int C = warpN * 64 + ni * 8;
            unsigned b[2];
            b[0] = __float_as_uint(sWt[(C + g) * S + k0 + t]);
            b[1] = __float_as_uint(sWt[(C + g) * S + k0 + t + 4]);
            mma_tf32(acc[0][ni], a[0], b);
            mma_tf32(acc[1][ni], a[1], b);
        }
    }

    // Per-row norms for LAYER1 prescale (rows depend only on mi)
    float nmA[2] = {1.f, 1.f}, nmB[2] = {1.f, 1.f};
    if (LAYER1) {
        #pragma unroll
        for (int mi = 0; mi < 2; mi++) {
            int r1 = row0 + warpM * 32 + mi * 16 + g;
            int r2 = r1 + 8;
            nmA[mi] = (r1 < N_NODES) ? g_norm[r1] : 0.f;
            nmB[mi] = (r2 < N_NODES) ? g_norm[r2] : 0.f;
        }
    }

    #pragma unroll
    for (int ni = 0; ni < 8; ni++) {
        int c = warpN * 64 + ni * 8 + 2 * t;
        float2 bb = *reinterpret_cast<const float2*>(&bias[c]);
        #pragma unroll
        for (int mi = 0; mi < 2; mi++) {
            int r1 = row0 + warpM * 32 + mi * 16 + g;
            int r2 = r1 + 8;
            float2 o1 = make_float2(acc[mi][ni][0] + bb.x,
                                    acc[mi][ni][1] + bb.y);
            float2 o2 = make_float2(acc[mi][ni][2] + bb.x,
                                    acc[mi][ni][3] + bb.y);
            if (LAYER1) {
                // relu, prescale by dst norm, store fp16 to g_h1
                o1.x = fmaxf(o1.x, 0.f) * nmA[mi];
                o1.y = fmaxf(o1.y, 0.f) * nmA[mi];
                o2.x = fmaxf(o2.x, 0.f) * nmB[mi];
                o2.y = fmaxf(o2.y, 0.f) * nmB[mi];
                if (r1 < N_NODES)
                    *reinterpret_cast<half2*>(&g_h1[r1 * D + c]) =
                        __floats2half2_rn(o1.x, o1.y);
                if (r2 < N_NODES)
                    *reinterpret_cast<half2*>(&g_h1[r2 * D + c]) =
                        __floats2half2_rn(o2.x, o2.y);
            } else {
                if (r1 < N_NODES)
                    *reinterpret_cast<float2*>(&outp[r1 * D + c]) = o1;
                if (r2 < N_NODES)
                    *reinterpret_cast<float2*>(&outp[r2 * D + c]) = o2;
            }
        }
    }
}

// ---------------------------------------------------------------------------
// Launch
// ---------------------------------------------------------------------------
extern "C" void kernel_launch(void* const* d_in, const int* in_sizes, int n_in,
                              void* d_out, int out_size) {
    const float* features = (const float*)d_in[0];
    const int*   src      = (const int*)d_in[1];
    const int*   dst      = (const int*)d_in[2];
    const float* W0       = (const float*)d_in[3];
    const float* b0       = (const float*)d_in[4];
    const float* W1       = (const float*)d_in[5];
    const float* b1       = (const float*)d_in[6];
    float* out = (float*)d_out;

    const int SMEM_EPI = 2 * D * S * sizeof(float);  // 135168 B
    cudaFuncSetAttribute(epilogue_kernel<true>,
                         cudaFuncAttributeMaxDynamicSharedMemorySize, SMEM_EPI);
    cudaFuncSetAttribute(epilogue_kernel<false>,
                         cudaFuncAttributeMaxDynamicSharedMemorySize, SMEM_EPI);

    const int nodesBlocks = (N_NODES + 255) / 256;
    const int edge4Blocks = (N_EDGES / 4 + 255) / 256;
    const int vecBlocks   = (N_NODES * (D / 4) + 255) / 256;
    const int aggBlocks   = (N_NODES + 7) / 8;
    const int epiBlocks   = (N_NODES + 127) / 128;

    // CSR build + prescale (5 launches)
    zero_kernel<<<nodesBlocks, 256>>>();
    hist_kernel<<<edge4Blocks, 256>>>((const int4*)dst);
    scan_kernel<<<NB, SCAN_BLK>>>();
    fill_kernel<<<edge4Blocks, 256>>>((const int4*)src, (const int4*)dst);
    prescale_kernel<<<vecBlocks, 256>>>((const float4*)features);

    // Layer 1
    aggregate_kernel<true><<<aggBlocks, 256>>>();
    epilogue_kernel<true><<<epiBlocks, 256, SMEM_EPI>>>(W0, b0, nullptr);

    // Layer 2
    aggregate_kernel<false><<<aggBlocks, 256>>>();
    epilogue_kernel<false><<<epiBlocks, 256, SMEM_EPI>>>(W1, b1, out);
}